// round 2
// baseline (speedup 1.0000x reference)
#include <cuda_runtime.h>

// Problem dims (hardcoded): B=4, C=256, H=128, W=128
#define Bn 4
#define Cc 256
#define Hh 128
#define Ww 128
#define CHW (Cc*Hh*Ww)

// ---------------- scratch (static device globals; no allocation allowed) ----
__device__ float g_bodyT[(size_t)Bn*Ww*Cc*Hh];   // [b*W+w][c][h]
__device__ float g_aughT[(size_t)Bn*Ww*Cc*Hh];   // raw aug_h in [b*W+w][c][h]
__device__ float g_outbuf[(size_t)Bn*Cc*Hh*Ww];  // gamma*(augh+augw)+body
__device__ float g_exmw[Bn*Hh*Cc];               // mean over w: rows [b*H+h][c]
__device__ float g_exmh[Bn*Ww*Cc];               // mean over h: rows [b*W+w][c]
__device__ float g_ench[Bn*Hh*Cc];               // enc_h [b][h][d] row-major
__device__ float g_encw[Bn*Ww*Cc];               // enc_w [b][w][d] row-major

// ---------------- kernel 1: row/col means of ex_layer ----------------------
// one block per (b,c); loads the 128x128 plane into smem, reduces both ways.
__global__ __launch_bounds__(128) void means_kernel(const float* __restrict__ ex) {
    extern __shared__ float sm[];               // 128 x 132
    int b = blockIdx.x >> 8, c = blockIdx.x & 255;
    const float4* src4 = (const float4*)(ex + ((size_t)(b*Cc + c))*Hh*Ww);
    int tid = threadIdx.x;
    for (int i4 = tid; i4 < (Hh*Ww)/4; i4 += 128) {
        int y = i4 >> 5, x4 = i4 & 31;
        float4 v = src4[i4];
        *(float4*)&sm[y*132 + x4*4] = v;
    }
    __syncthreads();
    float rs = 0.f, cs = 0.f;
    #pragma unroll 4
    for (int x = 0; x < Ww; x++) rs += sm[tid*132 + x];   // sum over w (row h=tid)
    #pragma unroll 4
    for (int y = 0; y < Hh; y++) cs += sm[y*132 + tid];   // sum over h (col w=tid)
    g_exmw[(b*Hh + tid)*Cc + c] = rs * (1.0f/Ww);
    g_exmh[(b*Ww + tid)*Cc + c] = cs * (1.0f/Hh);
}

// ---------------- kernel 2: small GEMM  C[r][d] = sum_c A[r][c]*Bm[d][c]+bias
// A: [R][256] row-major, Bm: [256][256] row-major (K contiguous both)
__global__ __launch_bounds__(256) void gemm_rk256(const float* __restrict__ A,
                                                  const float* __restrict__ Bm,
                                                  const float* __restrict__ bias,
                                                  float* __restrict__ Cm) {
    __shared__ float sA[64*33];
    __shared__ float sB[64*33];
    int r0 = blockIdx.x * 64, d0 = blockIdx.y * 64;
    int tid = threadIdx.x, ty = tid >> 4, tx = tid & 15;
    float acc[4][4] = {};
    for (int k0 = 0; k0 < 256; k0 += 32) {
        for (int idx = tid; idx < 64*32; idx += 256) {
            int row = idx >> 5, col = idx & 31;
            sA[row*33 + col] = A[(r0+row)*256 + k0 + col];
            sB[row*33 + col] = Bm[(d0+row)*256 + k0 + col];
        }
        __syncthreads();
        #pragma unroll
        for (int kk = 0; kk < 32; kk++) {
            float a[4], bb[4];
            #pragma unroll
            for (int i = 0; i < 4; i++) a[i]  = sA[(ty*4+i)*33 + kk];
            #pragma unroll
            for (int j = 0; j < 4; j++) bb[j] = sB[(tx*4+j)*33 + kk];
            #pragma unroll
            for (int i = 0; i < 4; i++)
                #pragma unroll
                for (int j = 0; j < 4; j++)
                    acc[i][j] = fmaf(a[i], bb[j], acc[i][j]);
        }
        __syncthreads();
    }
    #pragma unroll
    for (int i = 0; i < 4; i++)
        #pragma unroll
        for (int j = 0; j < 4; j++)
            Cm[(r0+ty*4+i)*256 + d0+tx*4+j] = acc[i][j] + bias[d0+tx*4+j];
}

// ---------------- kernel 3: transpose body -> bodyT[b,w,c,h] ---------------
__global__ __launch_bounds__(256) void transpose_bwch(const float* __restrict__ body) {
    __shared__ float t[32][33];
    int b = blockIdx.z >> 8, c = blockIdx.z & 255;
    int w0 = blockIdx.x*32, h0 = blockIdx.y*32;
    int tx = threadIdx.x, ty = threadIdx.y;   // 32 x 8
    const float* src = body + ((size_t)(b*Cc + c))*Hh*Ww;
    #pragma unroll
    for (int k = 0; k < 4; k++)
        t[ty + k*8][tx] = src[(h0 + ty + k*8)*Ww + w0 + tx];   // t[h_loc][w_loc]
    __syncthreads();
    #pragma unroll
    for (int k = 0; k < 4; k++) {
        int w = w0 + ty + k*8;
        g_bodyT[((size_t)(b*Ww + w)*Cc + c)*Hh + h0 + tx] = t[tx][ty + k*8];
    }
}

// ---------------- kernel 5: outbuf[b,c,h,w] += gamma * aughT[b,w,c,h] -------
__global__ __launch_bounds__(256) void transadd_kernel(const float* __restrict__ gammaP) {
    __shared__ float t[32][33];
    float g = gammaP[0];
    int b = blockIdx.z >> 8, c = blockIdx.z & 255;
    int w0 = blockIdx.x*32, h0 = blockIdx.y*32;
    int tx = threadIdx.x, ty = threadIdx.y;
    #pragma unroll
    for (int k = 0; k < 4; k++)   // read coalesced over h
        t[ty + k*8][tx] = g_aughT[((size_t)(b*Ww + w0 + ty + k*8)*Cc + c)*Hh + h0 + tx];
    __syncthreads();
    #pragma unroll
    for (int k = 0; k < 4; k++) {  // write coalesced over w
        int h = h0 + ty + k*8;
        size_t o = ((size_t)(b*Cc + c)*Hh + h)*Ww + w0 + tx;
        g_outbuf[o] += g * t[tx][ty + k*8];
    }
}

// ---------------- kernel 4: axial attention (shared by h-path & w-path) ----
// Per block: one i. feat [256][128] resident in smem.
//   S = feat @ enc  (K=128) -> softmax rows -> aug = P @ feat
// offsets: off = (i>>7)*CHW + (i&127)*s2 ; rows stride rstride (same feat/out)
#define ATTN_SMEM ((256*132 + 16*260 + 64*257)*4)
__global__ __launch_bounds__(256) void attn_kernel(const float* __restrict__ feat_base,
                                                   float* __restrict__ out_base,
                                                   const float* __restrict__ enc_all,
                                                   const float* __restrict__ gammaP,
                                                   int s2, int rstride, int add_body) {
    extern __shared__ float smem[];
    float* sf   = smem;                 // 256 x 132 (feat, padded)
    float* senc = sf + 256*132;         // 16 x 260 (enc K-chunk)
    float* sP   = senc + 16*260;        // 64 x 257 (scores / probs)
    int i = blockIdx.x;
    size_t off = (size_t)(i >> 7)*CHW + (size_t)(i & 127)*s2;
    const float* feat = feat_base + off;
    float* outp = out_base + off;
    const float* enc = enc_all + (size_t)(i & (Bn-1))*(128*256);
    int tid = threadIdx.x, ty = tid >> 4, tx = tid & 15;

    // load feat -> smem (float4)
    for (int i4 = tid; i4 < 256*32; i4 += 256) {
        int c = i4 >> 5, h4 = i4 & 31;
        float4 v = *(const float4*)&feat[(size_t)c*rstride + h4*4];
        *(float4*)&sf[c*132 + h4*4] = v;
    }
    __syncthreads();
    float gam = add_body ? gammaP[0] : 0.0f;

    #pragma unroll 1
    for (int ct = 0; ct < 4; ct++) {
        int c0 = ct*64;
        // ---- GEMM1: S[64][256] = feat[c0:c0+64,:] @ enc ----
        float acc[4][16] = {};
        #pragma unroll 1
        for (int kc = 0; kc < 8; kc++) {
            for (int i4 = tid; i4 < 16*64; i4 += 256) {
                int kk = i4 >> 6, d4 = i4 & 63;
                float4 v = *(const float4*)&enc[(kc*16 + kk)*256 + d4*4];
                *(float4*)&senc[kk*260 + d4*4] = v;
            }
            __syncthreads();
            #pragma unroll
            for (int kk = 0; kk < 16; kk++) {
                int k = kc*16 + kk;
                float a[4];
                #pragma unroll
                for (int r = 0; r < 4; r++) a[r] = sf[(c0 + ty*4 + r)*132 + k];
                #pragma unroll
                for (int j = 0; j < 16; j++) {
                    float bv = senc[kk*260 + tx + 16*j];
                    #pragma unroll
                    for (int r = 0; r < 4; r++)
                        acc[r][j] = fmaf(a[r], bv, acc[r][j]);
                }
            }
            __syncthreads();
        }
        #pragma unroll
        for (int r = 0; r < 4; r++)
            #pragma unroll
            for (int j = 0; j < 16; j++)
                sP[(ty*4 + r)*257 + tx + 16*j] = acc[r][j];
        __syncthreads();

        // ---- softmax over d (8 warps x 8 rows) ----
        {
            int wid = tid >> 5, lane = tid & 31;
            #pragma unroll 1
            for (int rr = 0; rr < 8; rr++) {
                int row = wid*8 + rr;
                float v[8], m = -1e30f;
                #pragma unroll
                for (int k = 0; k < 8; k++) { v[k] = sP[row*257 + lane + 32*k]; m = fmaxf(m, v[k]); }
                #pragma unroll
                for (int o = 16; o; o >>= 1) m = fmaxf(m, __shfl_xor_sync(0xffffffffu, m, o));
                float s = 0.f;
                #pragma unroll
                for (int k = 0; k < 8; k++) { v[k] = __expf(v[k] - m); s += v[k]; }
                #pragma unroll
                for (int o = 16; o; o >>= 1) s += __shfl_xor_sync(0xffffffffu, s, o);
                float inv = 1.0f / s;
                #pragma unroll
                for (int k = 0; k < 8; k++) sP[row*257 + lane + 32*k] = v[k]*inv;
            }
        }
        __syncthreads();

        // ---- GEMM2: aug[64][128] = P @ feat ----
        float a2[4][8] = {};
        #pragma unroll 4
        for (int d = 0; d < 256; d++) {
            float p[4];
            #pragma unroll
            for (int r = 0; r < 4; r++) p[r] = sP[(ty*4 + r)*257 + d];
            float4 f0 = *(float4*)&sf[d*132 + tx*8];
            float4 f1 = *(float4*)&sf[d*132 + tx*8 + 4];
            #pragma unroll
            for (int r = 0; r < 4; r++) {
                a2[r][0] = fmaf(p[r], f0.x, a2[r][0]);
                a2[r][1] = fmaf(p[r], f0.y, a2[r][1]);
                a2[r][2] = fmaf(p[r], f0.z, a2[r][2]);
                a2[r][3] = fmaf(p[r], f0.w, a2[r][3]);
                a2[r][4] = fmaf(p[r], f1.x, a2[r][4]);
                a2[r][5] = fmaf(p[r], f1.y, a2[r][5]);
                a2[r][6] = fmaf(p[r], f1.z, a2[r][6]);
                a2[r][7] = fmaf(p[r], f1.w, a2[r][7]);
            }
        }
        // ---- store ----
        #pragma unroll
        for (int r = 0; r < 4; r++) {
            int c = c0 + ty*4 + r;
            float o[8];
            if (add_body) {
                #pragma unroll
                for (int j = 0; j < 8; j++)
                    o[j] = fmaf(gam, a2[r][j], sf[c*132 + tx*8 + j]);
            } else {
                #pragma unroll
                for (int j = 0; j < 8; j++) o[j] = a2[r][j];
            }
            float* dst = outp + (size_t)c*rstride + tx*8;
            *(float4*)dst       = make_float4(o[0], o[1], o[2], o[3]);
            *(float4*)(dst + 4) = make_float4(o[4], o[5], o[6], o[7]);
        }
        __syncthreads();
    }
}

// ---------------- kernel 6: 3x3 conv + BN + ReLU ---------------------------
// block: 64 c_out x (8h x 32w) spatial, loops 16 c_in chunks of 16
#define CONV_SMEM ((64*148 + 16*350)*4)
__global__ __launch_bounds__(256) void conv_kernel(const float* __restrict__ cw,
                                                   const float* __restrict__ bnw,
                                                   const float* __restrict__ bnb,
                                                   float* __restrict__ out) {
    extern __shared__ float smem[];
    float* wt  = smem;              // 64 x 148  (64 co x 144 wts, padded)
    float* sin = wt + 64*148;       // 16 x 10 x 35
    int co0 = blockIdx.x * 64;
    int hti = blockIdx.y >> 2, wti = blockIdx.y & 3;
    int b = blockIdx.z;
    int h0 = hti*8, w0 = wti*32;
    int tid = threadIdx.x;
    int cg = tid >> 6, sg = tid & 63;
    int hh = sg >> 3, w4 = (sg & 7) << 2;
    float acc[16][4] = {};
    const float4* cw4 = (const float4*)cw;

    #pragma unroll 1
    for (int cic = 0; cic < 16; cic++) {
        int ci0 = cic*16;
        // weights: 64 rows x 36 float4 each
        for (int i4 = tid; i4 < 64*36; i4 += 256) {
            int row = i4/36, o4 = i4 - row*36;
            float4 v = cw4[(size_t)(co0+row)*576 + (size_t)cic*36 + o4];
            *(float4*)&wt[row*148 + o4*4] = v;
        }
        // input tile with halo + zero pad
        for (int idx = tid; idx < 16*10*34; idx += 256) {
            int ci = idx/340, rem = idx - ci*340;
            int yy = rem/34, xx = rem - yy*34;
            int y = h0 + yy - 1, x = w0 + xx - 1;
            float v = 0.f;
            if (y >= 0 && y < Hh && x >= 0 && x < Ww)
                v = g_outbuf[((size_t)(b*Cc + ci0 + ci)*Hh + y)*Ww + x];
            sin[ci*350 + yy*35 + xx] = v;
        }
        __syncthreads();
        #pragma unroll 2
        for (int ci = 0; ci < 16; ci++) {
            #pragma unroll
            for (int ky = 0; ky < 3; ky++) {
                float iv[6];
                #pragma unroll
                for (int t = 0; t < 6; t++) iv[t] = sin[ci*350 + (hh+ky)*35 + w4 + t];
                #pragma unroll
                for (int kx = 0; kx < 3; kx++) {
                    #pragma unroll
                    for (int j = 0; j < 16; j++) {
                        float wv = wt[(cg*16 + j)*148 + ci*9 + ky*3 + kx];
                        #pragma unroll
                        for (int sp = 0; sp < 4; sp++)
                            acc[j][sp] = fmaf(wv, iv[kx + sp], acc[j][sp]);
                    }
                }
            }
        }
        __syncthreads();
    }
    const float inv = rsqrtf(1.0f + 1e-5f);
    #pragma unroll
    for (int j = 0; j < 16; j++) {
        int co = co0 + cg*16 + j;
        float sc = bnw[co]*inv, bb = bnb[co];
        float4 r;
        r.x = fmaxf(fmaf(acc[j][0], sc, bb), 0.f);
        r.y = fmaxf(fmaf(acc[j][1], sc, bb), 0.f);
        r.z = fmaxf(fmaf(acc[j][2], sc, bb), 0.f);
        r.w = fmaxf(fmaf(acc[j][3], sc, bb), 0.f);
        *(float4*)&out[((size_t)(b*Cc + co)*Hh + h0 + hh)*Ww + w0 + w4] = r;
    }
}

// ---------------- host launcher --------------------------------------------
extern "C" void kernel_launch(void* const* d_in, const int* in_sizes, int n_in,
                              void* d_out, int out_size) {
    const float* body  = (const float*)d_in[0];
    const float* ex    = (const float*)d_in[1];
    const float* W1    = (const float*)d_in[2];
    const float* b1    = (const float*)d_in[3];
    const float* W2    = (const float*)d_in[4];
    const float* b2    = (const float*)d_in[5];
    const float* cw    = (const float*)d_in[6];
    const float* bnw   = (const float*)d_in[7];
    const float* bnb   = (const float*)d_in[8];
    const float* gamma = (const float*)d_in[9];
    float* out = (float*)d_out;

    cudaFuncSetAttribute(means_kernel, cudaFuncAttributeMaxDynamicSharedMemorySize, 128*132*4);
    cudaFuncSetAttribute(attn_kernel,  cudaFuncAttributeMaxDynamicSharedMemorySize, ATTN_SMEM);
    cudaFuncSetAttribute(conv_kernel,  cudaFuncAttributeMaxDynamicSharedMemorySize, CONV_SMEM);

    void *p_exmw, *p_exmh, *p_ench, *p_encw, *p_bodyT, *p_aughT, *p_outbuf;
    cudaGetSymbolAddress(&p_exmw, g_exmw);
    cudaGetSymbolAddress(&p_exmh, g_exmh);
    cudaGetSymbolAddress(&p_ench, g_ench);
    cudaGetSymbolAddress(&p_encw, g_encw);
    cudaGetSymbolAddress(&p_bodyT, g_bodyT);
    cudaGetSymbolAddress(&p_aughT, g_aughT);
    cudaGetSymbolAddress(&p_outbuf, g_outbuf);

    // 1. means of ex_layer (both axes)
    means_kernel<<<Bn*Cc, 128, 128*132*4>>>(ex);
    // 2. enc_h = exmw @ W1^T + b1 ; enc_w = exmh @ W2^T + b2
    gemm_rk256<<<dim3(8,4), 256>>>((const float*)p_exmw, W1, b1, (float*)p_ench);
    gemm_rk256<<<dim3(8,4), 256>>>((const float*)p_exmh, W2, b2, (float*)p_encw);
    // 3. body -> bodyT[b,w,c,h]
    transpose_bwch<<<dim3(4,4,Bn*Cc), dim3(32,8)>>>(body);
    // 4a. h-path: feat = bodyT rows, write raw aug_h to g_aughT
    attn_kernel<<<Bn*Ww, 256, ATTN_SMEM>>>((const float*)p_bodyT, (float*)p_aughT,
                                           (const float*)p_ench, gamma,
                                           Cc*Hh, Hh, 0);
    // 4b. w-path: feat = body rows, write gamma*aug_w + body to g_outbuf
    attn_kernel<<<Bn*Hh, 256, ATTN_SMEM>>>(body, (float*)p_outbuf,
                                           (const float*)p_encw, gamma,
                                           Ww, Hh*Ww, 1);
    // 5. outbuf += gamma * aug_h (transposed)
    transadd_kernel<<<dim3(4,4,Bn*Cc), dim3(32,8)>>>(gamma);
    // 6. conv3x3 + BN + ReLU -> d_out
    conv_kernel<<<dim3(4,64,Bn), 256, CONV_SMEM>>>(cw, bnw, bnb, out);
}